// round 16
// baseline (speedup 1.0000x reference)
#include <cuda_runtime.h>
#include <cuda_fp16.h>
#include <math.h>
#include <stdint.h>

#define OUT_N  2048
#define IN_K   2048
#define M_ROWS 8192
#define RANK   4

// ---------------- scratch (static device globals; no runtime alloc) --------
__device__ float  g_coef[8];                   // [0..3]=g_r/||A_r||, [4..7]=1/||B_r||
__device__ __half g_W[(size_t)OUT_N * IN_K];   // fp16 effective weight (8 MB)
__device__ __half g_X[(size_t)M_ROWS * IN_K];  // fp16 activations (32 MB)

// sync array: [0]=prep ticket  [1]=tile ticket  [2]=coef flag
//             [3..35)=fx per K-chunk  [35..67)=fw per K-chunk  [67]=done count
__device__ int g_syncArr[68];   // zero-initialized at load; self-reset each run
#define SY_PREP 0
#define SY_TILE 1
#define SY_COEF 2
#define SY_FX   3
#define SY_FW   35
#define SY_DONE 67
#define NPREP   385              // 1 norm + 256 X slices + 128 W slices
#define NTILES  1024

__device__ __forceinline__ uint32_t h2_bits(__half2 h) {
    union { __half2 h; uint32_t u; } cvt;
    cvt.h = h;
    return cvt.u;
}

// ---------------- prep ticket workers ---------------------------------------
__device__ void do_norm(const float* __restrict__ sA, const float* __restrict__ sB,
                        const float* __restrict__ mag, int tid)
{
    __shared__ float red[8][8];
    const int lid = tid & 31, wid = tid >> 5;
    float s[8] = {0.f, 0.f, 0.f, 0.f, 0.f, 0.f, 0.f, 0.f};
    const float4* A4 = (const float4*)sA;
#pragma unroll
    for (int i = 0; i < 8; ++i) {
        float4 v = A4[tid + i * 256];
        s[0] += v.x * v.x; s[1] += v.y * v.y; s[2] += v.z * v.z; s[3] += v.w * v.w;
    }
    const float4* B4 = (const float4*)sB;
#pragma unroll
    for (int r = 0; r < 4; ++r)
#pragma unroll
        for (int j = 0; j < 2; ++j) {
            float4 v = B4[r * 512 + tid + j * 256];
            s[4 + r] += v.x * v.x + v.y * v.y + v.z * v.z + v.w * v.w;
        }
#pragma unroll
    for (int off = 16; off; off >>= 1)
#pragma unroll
        for (int q = 0; q < 8; ++q)
            s[q] += __shfl_xor_sync(0xffffffff, s[q], off);
    if (lid == 0)
#pragma unroll
        for (int q = 0; q < 8; ++q) red[wid][q] = s[q];
    __syncthreads();
    if (tid == 0) {
        float t[8];
#pragma unroll
        for (int q = 0; q < 8; ++q) {
            t[q] = red[0][q];
            for (int w = 1; w < 8; ++w) t[q] += red[w][q];
        }
#pragma unroll
        for (int r = 0; r < 4; ++r) {
            float nrmA = fmaxf(sqrtf(t[r]), 1e-6f);
            float m = mag[r];
            float g = (m > 20.f ? m : log1pf(expf(m))) + 1e-6f;
            g_coef[r] = g / nrmA;
            g_coef[4 + r] = 1.f / fmaxf(sqrtf(t[4 + r]), 1e-6f);
        }
        __threadfence();
        atomicExch(&g_syncArr[SY_COEF], 1);
    }
}

// X slice: chunk kt (cols [kt*64,+64)), slice s (rows [s*1024,+1024))
__device__ void do_xslice(const float* __restrict__ x, int kt, int s, int tid)
{
    const int colbase = kt * 64;
#pragma unroll 4
    for (int k = 0; k < 64; ++k) {
        const int j = tid + (k << 8);
        const int row = s * 1024 + (j >> 4);
        const int c4 = j & 15;
        const size_t off = (size_t)row * IN_K + colbase + c4 * 4;
        float4 v = *(const float4*)&x[off];
        uint2 o;
        o.x = h2_bits(__floats2half2_rn(v.x, v.y));
        o.y = h2_bits(__floats2half2_rn(v.z, v.w));
        *(uint2*)&g_X[off] = o;
    }
    __threadfence();
    __syncthreads();
    if (tid == 0) atomicAdd(&g_syncArr[SY_FX + kt], 1);
}

// W slice: chunk kt, slice s (rows [s*512,+512))
__device__ void do_wslice(const int* __restrict__ indices, const float* __restrict__ lut,
                          const float* __restrict__ sA, const float* __restrict__ sB,
                          int kt, int s, int tid)
{
    __shared__ float sLut[16];
    __shared__ float sC[8];
    if (tid == 0) {
        while (atomicAdd(&g_syncArr[SY_COEF], 0) == 0) { }
    }
    __syncthreads();
    if (tid < 16) sLut[tid] = lut[tid];
    if (tid < 8)  sC[tid] = g_coef[tid];
    __syncthreads();
    const float c0 = sC[0] * sC[4], c1 = sC[1] * sC[5];
    const float c2 = sC[2] * sC[6], c3 = sC[3] * sC[7];
    const int colbase = kt * 64;

#pragma unroll 2
    for (int k = 0; k < 32; ++k) {
        const int j = tid + (k << 8);
        const int row = s * 512 + (j >> 4);
        const int g = j & 15;
        const float4 a4 = *(const float4*)&sA[row * 4];
        const float k0 = fabsf(a4.x) * c0, k1 = fabsf(a4.y) * c1;
        const float k2 = fabsf(a4.z) * c2, k3 = fabsf(a4.w) * c3;
        const size_t off = (size_t)row * IN_K + colbase + g * 4;
        const int cb = colbase + g * 4;
        const int4 idx = *(const int4*)&indices[off];
        const float4 b0 = *(const float4*)&sB[0 * IN_K + cb];
        const float4 b1 = *(const float4*)&sB[1 * IN_K + cb];
        const float4 b2 = *(const float4*)&sB[2 * IN_K + cb];
        const float4 b3 = *(const float4*)&sB[3 * IN_K + cb];
        __half2 w01 = __floats2half2_rn(
            sLut[idx.x] * (k0 * fabsf(b0.x) + k1 * fabsf(b1.x) + k2 * fabsf(b2.x) + k3 * fabsf(b3.x)),
            sLut[idx.y] * (k0 * fabsf(b0.y) + k1 * fabsf(b1.y) + k2 * fabsf(b2.y) + k3 * fabsf(b3.y)));
        __half2 w23 = __floats2half2_rn(
            sLut[idx.z] * (k0 * fabsf(b0.z) + k1 * fabsf(b1.z) + k2 * fabsf(b2.z) + k3 * fabsf(b3.z)),
            sLut[idx.w] * (k0 * fabsf(b0.w) + k1 * fabsf(b1.w) + k2 * fabsf(b2.w) + k3 * fabsf(b3.w)));
        uint2 packed = make_uint2(h2_bits(w01), h2_bits(w23));
        *(uint2*)&g_W[off] = packed;
    }
    __threadfence();
    __syncthreads();
    if (tid == 0) atomicAdd(&g_syncArr[SY_FW + kt], 1);
}

// ---------------- GEMM config (R8, race-fixed) ------------------------------
#define BM 128
#define BN 128
#define BK 64
#define PADH 72
#define STG_HALVES ((BM + BN) * PADH)
#define STG_BYTES (STG_HALVES * 2)
#define AS_OFF 0
#define BS_OFF (BM * PADH)
#define NKT (IN_K / BK)                // 32
#define NSTG 3
#define DYN_SMEM (NSTG * STG_BYTES)    // 110,592 B

__device__ __forceinline__ uint32_t smem_u32(const void* p) {
    uint32_t a;
    asm("{ .reg .u64 t; cvta.to.shared.u64 t, %1; cvt.u32.u64 %0, t; }" : "=r"(a) : "l"(p));
    return a;
}
__device__ __forceinline__ void cp16(void* dst, const void* src) {
    uint32_t d;
    asm("{ .reg .u64 t; cvta.to.shared.u64 t, %1; cvt.u32.u64 %0, t; }" : "=r"(d) : "l"(dst));
    asm volatile("cp.async.cg.shared.global [%0], [%1], 16;" :: "r"(d), "l"(src));
}
__device__ __forceinline__ void cp_commit() {
    asm volatile("cp.async.commit_group;" ::: "memory");
}
template<int N>
__device__ __forceinline__ void cp_wait() {
    asm volatile("cp.async.wait_group %0;" :: "n"(N) : "memory");
}
__device__ __forceinline__ void ldsm_x4(uint32_t* r, uint32_t addr) {
    asm volatile("ldmatrix.sync.aligned.m8n8.x4.shared.b16 {%0,%1,%2,%3}, [%4];"
                 : "=r"(r[0]), "=r"(r[1]), "=r"(r[2]), "=r"(r[3]) : "r"(addr));
}
__device__ __forceinline__ void mma16(float& c0, float& c1, float& c2, float& c3,
                                      uint32_t a0, uint32_t a1, uint32_t a2, uint32_t a3,
                                      uint32_t b0, uint32_t b1) {
    asm volatile(
        "mma.sync.aligned.m16n8k16.row.col.f32.f16.f16.f32 "
        "{%0,%1,%2,%3}, {%4,%5,%6,%7}, {%8,%9}, {%0,%1,%2,%3};"
        : "+f"(c0), "+f"(c1), "+f"(c2), "+f"(c3)
        : "r"(a0), "r"(a1), "r"(a2), "r"(a3), "r"(b0), "r"(b1));
}

__device__ __forceinline__ void issue_stage(__half* smem, int stage, int kbase,
                                            const __half* Ag, const __half* Bg, int tid)
{
    __half* as = smem + (size_t)stage * STG_HALVES + AS_OFF;
    __half* bs = smem + (size_t)stage * STG_HALVES + BS_OFF;
#pragma unroll
    for (int i = 0; i < 4; ++i) {
        int c = tid + i * 256, row = c >> 3, kc = (c & 7) << 3;
        cp16(as + row * PADH + kc, Ag + (size_t)row * IN_K + kbase + kc);
    }
#pragma unroll
    for (int i = 0; i < 4; ++i) {
        int c = tid + i * 256, row = c >> 3, kc = (c & 7) << 3;
        cp16(bs + row * PADH + kc, Bg + (size_t)row * IN_K + kbase + kc);
    }
    cp_commit();
}

__device__ __forceinline__ void wait_chunk(int c) {
    while (atomicAdd(&g_syncArr[SY_FX + c], 0) < 8 ||
           atomicAdd(&g_syncArr[SY_FW + c], 0) < 4) { }
}

__device__ __forceinline__ void compute_iter(uint32_t aQ, uint32_t bQ,
                                             float (*acc)[4][4])
{
#pragma unroll
    for (int ks = 0; ks < 4; ++ks) {
        const uint32_t kOff = (uint32_t)(ks * 32);
        uint32_t a[4][4];
#pragma unroll
        for (int mt = 0; mt < 4; ++mt)
            ldsm_x4(a[mt], aQ + (uint32_t)(mt * 16 * PADH * 2) + kOff);
        uint32_t bb[2][4];
#pragma unroll
        for (int j = 0; j < 2; ++j)
            ldsm_x4(bb[j], bQ + (uint32_t)(j * 16 * PADH * 2) + kOff);
#pragma unroll
        for (int mt = 0; mt < 4; ++mt)
#pragma unroll
            for (int nt = 0; nt < 4; ++nt)
                mma16(acc[mt][nt][0], acc[mt][nt][1], acc[mt][nt][2], acc[mt][nt][3],
                      a[mt][0], a[mt][1], a[mt][2], a[mt][3],
                      bb[nt >> 1][(nt & 1) * 2], bb[nt >> 1][(nt & 1) * 2 + 1]);
    }
}

// ---------------- mega kernel: prep tickets + flag-gated GEMM ---------------
__global__ __launch_bounds__(256, 2) void mega_kernel(const int* __restrict__ indices,
                                                      const float* __restrict__ lut,
                                                      const float* __restrict__ sA,
                                                      const float* __restrict__ sB,
                                                      const float* __restrict__ mag,
                                                      const float* __restrict__ x,
                                                      const float* __restrict__ bias,
                                                      float* __restrict__ Y)
{
    extern __shared__ __half smem[];
    __shared__ int sTick;
    const int tid = threadIdx.x;

    // ---- Phase A: prep tickets (work-stealing; producers are resident) ----
    for (;;) {
        if (tid == 0) sTick = atomicAdd(&g_syncArr[SY_PREP], 1);
        __syncthreads();
        const int t = sTick;
        __syncthreads();
        if (t >= NPREP) break;
        if (t == 0)            do_norm(sA, sB, mag, tid);
        else if (t < 257)      do_xslice(x, (t - 1) >> 3, (t - 1) & 7, tid);
        else                   do_wslice(indices, lut, sA, sB, (t - 257) >> 2, (t - 257) & 3, tid);
        __syncthreads();
    }

    // ---- Phase B: one GEMM tile per CTA, flag-gated K-chunk consumption ----
    if (tid == 0) sTick = atomicAdd(&g_syncArr[SY_TILE], 1);
    __syncthreads();
    const int tile = sTick;
    const int bm = (tile >> 4) * BM;
    const int bn = (tile & 15) * BN;

    const uint32_t sbase = smem_u32(smem);
    const int wid = tid >> 5, lane = tid & 31;
    const int warp_m = wid & 1, warp_n = wid >> 1;
    const int gid = lane >> 2, tig = lane & 3;

    const __half* Ag = g_X + (size_t)bm * IN_K;
    const __half* Bg = g_W + (size_t)bn * IN_K;

    const int lg = lane >> 3, lr = lane & 7;
    const uint32_t aLane = (uint32_t)(((warp_m * 64 + (lg & 1) * 8 + lr) * PADH
                                       + (lg >> 1) * 8) * 2);
    const uint32_t bLane = (uint32_t)(((warp_n * 32 + (lg >> 1) * 8 + lr) * PADH
                                       + (lg & 1) * 8 + BS_OFF) * 2);

    float acc[4][4][4];
#pragma unroll
    for (int i = 0; i < 4; ++i)
#pragma unroll
        for (int j = 0; j < 4; ++j)
#pragma unroll
            for (int q = 0; q < 4; ++q) acc[i][j][q] = 0.f;

    // prologue: gate chunks 0,1 then issue stages 0,1
    if (tid == 0) { wait_chunk(0); wait_chunk(1); }
    __syncthreads();
    issue_stage(smem, 0, 0 * BK, Ag, Bg, tid);
    issue_stage(smem, 1, 1 * BK, Ag, Bg, tid);

    for (int kt = 0; kt < NKT - 1; ++kt) {
        cp_wait<1>();
        const int ldk = kt + 2;
        if (tid == 0 && ldk < NKT) wait_chunk(ldk);
        __syncthreads();

        if (ldk < NKT)
            issue_stage(smem, ldk % NSTG, ldk * BK, Ag, Bg, tid);

        const uint32_t stq = sbase + (uint32_t)(kt % NSTG) * STG_BYTES;
        compute_iter(stq + aLane, stq + bLane, acc);
    }
    {   // peeled final iteration: full drain
        cp_wait<0>();
        __syncthreads();
        const uint32_t stq = sbase + (uint32_t)((NKT - 1) % NSTG) * STG_BYTES;
        compute_iter(stq + aLane, stq + bLane, acc);
    }

    // ---- epilogue: bias + store ----
#pragma unroll
    for (int mt = 0; mt < 4; ++mt) {
        const int row0 = bm + warp_m * 64 + mt * 16 + gid;
#pragma unroll
        for (int nt = 0; nt < 4; ++nt) {
            const int col = bn + warp_n * 32 + nt * 8 + tig * 2;
            const float bx = __ldg(&bias[col]);
            const float by = __ldg(&bias[col + 1]);
            float2 v0 = make_float2(acc[mt][nt][0] + bx, acc[mt][nt][1] + by);
            float2 v1 = make_float2(acc[mt][nt][2] + bx, acc[mt][nt][3] + by);
            *(float2*)&Y[(size_t)row0 * OUT_N + col] = v0;
            *(float2*)&Y[(size_t)(row0 + 8) * OUT_N + col] = v1;
        }
    }

    // ---- self-reset: last CTA zeroes all sync state for the next replay ----
    __syncthreads();
    if (tid == 0) {
        __threadfence();
        int v = atomicAdd(&g_syncArr[SY_DONE], 1);
        if (v == NTILES - 1) {
#pragma unroll
            for (int i = 0; i < 68; ++i) g_syncArr[i] = 0;
            __threadfence();
        }
    }
}

// ---------------- launch ----------------------------------------------------
extern "C" void kernel_launch(void* const* d_in, const int* in_sizes, int n_in,
                              void* d_out, int out_size)
{
    const float* x       = (const float*)d_in[0];  // [4, 2048, 2048]
    const int*   indices = (const int*)  d_in[1];  // [2048, 2048]
    const float* lut     = (const float*)d_in[2];  // [16]
    const float* sA      = (const float*)d_in[3];  // [2048, 4]
    const float* sB      = (const float*)d_in[4];  // [4, 2048]
    const float* mag     = (const float*)d_in[5];  // [4]
    const float* bias    = (const float*)d_in[6];  // [2048]
    float* y = (float*)d_out;                      // [4, 2048, 2048]

    cudaFuncSetAttribute(mega_kernel, cudaFuncAttributeMaxDynamicSharedMemorySize, DYN_SMEM);

    mega_kernel<<<NTILES, 256, DYN_SMEM>>>(indices, lut, sA, sB, mag, x, bias, y);
}

// round 17
// speedup vs baseline: 1.2021x; 1.2021x over previous
#include <cuda_runtime.h>
#include <cuda_fp16.h>
#include <math.h>
#include <stdint.h>

#define OUT_N  2048
#define IN_K   2048
#define M_ROWS 8192
#define RANK   4

// ---------------- scratch (static device globals; no runtime alloc) --------
__device__ float  g_coef[8];                   // [0..3]=g_r/||A_r||, [4..7]=1/||B_r||
__device__ int    g_flag = 0;                  // release flag for g_coef
__device__ __half g_W[(size_t)OUT_N * IN_K];   // fp16 effective weight (8 MB)
__device__ __half g_X[(size_t)M_ROWS * IN_K];  // fp16 activations (32 MB)

__device__ __forceinline__ uint32_t h2_bits(__half2 h) {
    union { __half2 h; uint32_t u; } cvt;
    cvt.h = h;
    return cvt.u;
}

// ---------------- Fused prep: norms (block 0) + convert X + build W ---------
#define XBLOCKS ((M_ROWS * IN_K) / (256 * 8))   // 8192
#define PREP_GRID (1 + XBLOCKS + OUT_N)

__global__ __launch_bounds__(256) void prep_fused_kernel(const int* __restrict__ indices,
                                                         const float* __restrict__ lut,
                                                         const float* __restrict__ sA,
                                                         const float* __restrict__ sB,
                                                         const float* __restrict__ mag,
                                                         const float* __restrict__ x)
{
    const int tid = threadIdx.x;

    if (blockIdx.x == 0) {
        __shared__ float red[8][8];
        const int lid = tid & 31, wid = tid >> 5;
        float s[8] = {0.f, 0.f, 0.f, 0.f, 0.f, 0.f, 0.f, 0.f};
        const float4* A4 = (const float4*)sA;
#pragma unroll
        for (int i = 0; i < 8; ++i) {
            float4 v = A4[tid + i * 256];
            s[0] += v.x * v.x; s[1] += v.y * v.y; s[2] += v.z * v.z; s[3] += v.w * v.w;
        }
        const float4* B4 = (const float4*)sB;
#pragma unroll
        for (int r = 0; r < 4; ++r)
#pragma unroll
            for (int j = 0; j < 2; ++j) {
                float4 v = B4[r * 512 + tid + j * 256];
                s[4 + r] += v.x * v.x + v.y * v.y + v.z * v.z + v.w * v.w;
            }
#pragma unroll
        for (int off = 16; off; off >>= 1)
#pragma unroll
            for (int q = 0; q < 8; ++q)
                s[q] += __shfl_xor_sync(0xffffffff, s[q], off);
        if (lid == 0)
#pragma unroll
            for (int q = 0; q < 8; ++q) red[wid][q] = s[q];
        __syncthreads();
        if (tid == 0) {
            float t[8];
#pragma unroll
            for (int q = 0; q < 8; ++q) {
                t[q] = red[0][q];
                for (int w = 1; w < 8; ++w) t[q] += red[w][q];
            }
#pragma unroll
            for (int r = 0; r < 4; ++r) {
                float nrmA = fmaxf(sqrtf(t[r]), 1e-6f);
                float m = mag[r];
                float g = (m > 20.f ? m : log1pf(expf(m))) + 1e-6f;
                g_coef[r] = g / nrmA;
                g_coef[4 + r] = 1.f / fmaxf(sqrtf(t[4 + r]), 1e-6f);
            }
            __threadfence();
            atomicExch(&g_flag, 1);
        }
        return;
    }

    if (blockIdx.x < 1 + XBLOCKS) {
        size_t i = ((size_t)(blockIdx.x - 1) * 256 + tid) * 8;
        float4 v0 = *(const float4*)&x[i];
        float4 v1 = *(const float4*)&x[i + 4];
        uint4 out;
        out.x = h2_bits(__floats2half2_rn(v0.x, v0.y));
        out.y = h2_bits(__floats2half2_rn(v0.z, v0.w));
        out.z = h2_bits(__floats2half2_rn(v1.x, v1.y));
        out.w = h2_bits(__floats2half2_rn(v1.z, v1.w));
        *(uint4*)&g_X[i] = out;
        return;
    }

    __shared__ float lsh[16];
    __shared__ float ash[RANK];
    const int o = blockIdx.x - 1 - XBLOCKS;

    if (tid == 0) {
        while (atomicAdd(&g_flag, 0) == 0) { }
    }
    __syncthreads();
    __threadfence();

    if (tid < 16) lsh[tid] = lut[tid];
    if (tid < RANK) ash[tid] = fabsf(sA[o * RANK + tid]) * g_coef[tid];
    __syncthreads();

    const float k0 = ash[0] * g_coef[4], k1 = ash[1] * g_coef[5];
    const float k2 = ash[2] * g_coef[6], k3 = ash[3] * g_coef[7];

#pragma unroll
    for (int half = 0; half < 2; ++half) {
        const int i0 = tid * 4 + half * 1024;
        const int4 idx = *(const int4*)&indices[(size_t)o * IN_K + i0];
        const float4 b0 = *(const float4*)&sB[0 * IN_K + i0];
        const float4 b1 = *(const float4*)&sB[1 * IN_K + i0];
        const float4 b2 = *(const float4*)&sB[2 * IN_K + i0];
        const float4 b3 = *(const float4*)&sB[3 * IN_K + i0];

        __half2 w01 = __floats2half2_rn(
            lsh[idx.x] * (k0 * fabsf(b0.x) + k1 * fabsf(b1.x) + k2 * fabsf(b2.x) + k3 * fabsf(b3.x)),
            lsh[idx.y] * (k0 * fabsf(b0.y) + k1 * fabsf(b1.y) + k2 * fabsf(b2.y) + k3 * fabsf(b3.y)));
        __half2 w23 = __floats2half2_rn(
            lsh[idx.z] * (k0 * fabsf(b0.z) + k1 * fabsf(b1.z) + k2 * fabsf(b2.z) + k3 * fabsf(b3.z)),
            lsh[idx.w] * (k0 * fabsf(b0.w) + k1 * fabsf(b1.w) + k2 * fabsf(b2.w) + k3 * fabsf(b3.w)));
        uint2 packed = make_uint2(h2_bits(w01), h2_bits(w23));
        *(uint2*)&g_W[(size_t)o * IN_K + i0] = packed;
    }
}

// ---------------- GEMM: fp16 mma.sync, persistent CTAs ----------------------
// CTA 128x128, 256 threads (8 warps of 64x32), BK=64, 3 stages, 2 CTAs/SM,
// 296 persistent CTAs with inter-tile stage prefetch.
#define BM 128
#define BN 128
#define BK 64
#define PADH 72
#define STG_HALVES ((BM + BN) * PADH)
#define STG_BYTES (STG_HALVES * 2)
#define AS_OFF 0
#define BS_OFF (BM * PADH)
#define NKT (IN_K / BK)                // 32
#define NSTG 3
#define DYN_SMEM (NSTG * STG_BYTES)    // 110,592 B
#define NTILES 1024
#define NCTA   296

__device__ __forceinline__ uint32_t smem_u32(const void* p) {
    uint32_t a;
    asm("{ .reg .u64 t; cvta.to.shared.u64 t, %1; cvt.u32.u64 %0, t; }" : "=r"(a) : "l"(p));
    return a;
}
__device__ __forceinline__ void cp16(void* dst, const void* src) {
    uint32_t d;
    asm("{ .reg .u64 t; cvta.to.shared.u64 t, %1; cvt.u32.u64 %0, t; }" : "=r"(d) : "l"(dst));
    asm volatile("cp.async.cg.shared.global [%0], [%1], 16;" :: "r"(d), "l"(src));
}
__device__ __forceinline__ void cp_commit() {
    asm volatile("cp.async.commit_group;" ::: "memory");
}
template<int N>
__device__ __forceinline__ void cp_wait() {
    asm volatile("cp.async.wait_group %0;" :: "n"(N) : "memory");
}
__device__ __forceinline__ void ldsm_x4(uint32_t* r, uint32_t addr) {
    asm volatile("ldmatrix.sync.aligned.m8n8.x4.shared.b16 {%0,%1,%2,%3}, [%4];"
                 : "=r"(r[0]), "=r"(r[1]), "=r"(r[2]), "=r"(r[3]) : "r"(addr));
}
__device__ __forceinline__ void mma16(float& c0, float& c1, float& c2, float& c3,
                                      uint32_t a0, uint32_t a1, uint32_t a2, uint32_t a3,
                                      uint32_t b0, uint32_t b1) {
    asm volatile(
        "mma.sync.aligned.m16n8k16.row.col.f32.f16.f16.f32 "
        "{%0,%1,%2,%3}, {%4,%5,%6,%7}, {%8,%9}, {%0,%1,%2,%3};"
        : "+f"(c0), "+f"(c1), "+f"(c2), "+f"(c3)
        : "r"(a0), "r"(a1), "r"(a2), "r"(a3), "r"(b0), "r"(b1));
}

__device__ __forceinline__ void issue_stage(__half* smem, int stage, int kbase,
                                            const __half* Ag, const __half* Bg, int tid)
{
    __half* as = smem + (size_t)stage * STG_HALVES + AS_OFF;
    __half* bs = smem + (size_t)stage * STG_HALVES + BS_OFF;
#pragma unroll
    for (int i = 0; i < 4; ++i) {
        int c = tid + i * 256, row = c >> 3, kc = (c & 7) << 3;
        cp16(as + row * PADH + kc, Ag + (size_t)row * IN_K + kbase + kc);
    }
#pragma unroll
    for (int i = 0; i < 4; ++i) {
        int c = tid + i * 256, row = c >> 3, kc = (c & 7) << 3;
        cp16(bs + row * PADH + kc, Bg + (size_t)row * IN_K + kbase + kc);
    }
    cp_commit();
}

__device__ __forceinline__ void compute_iter(uint32_t aQ, uint32_t bQ,
                                             float (*acc)[4][4])
{
#pragma unroll
    for (int ks = 0; ks < 4; ++ks) {
        const uint32_t kOff = (uint32_t)(ks * 32);
        uint32_t a[4][4];
#pragma unroll
        for (int mt = 0; mt < 4; ++mt)
            ldsm_x4(a[mt], aQ + (uint32_t)(mt * 16 * PADH * 2) + kOff);
        uint32_t bb[2][4];
#pragma unroll
        for (int j = 0; j < 2; ++j)
            ldsm_x4(bb[j], bQ + (uint32_t)(j * 16 * PADH * 2) + kOff);
#pragma unroll
        for (int mt = 0; mt < 4; ++mt)
#pragma unroll
            for (int nt = 0; nt < 4; ++nt)
                mma16(acc[mt][nt][0], acc[mt][nt][1], acc[mt][nt][2], acc[mt][nt][3],
                      a[mt][0], a[mt][1], a[mt][2], a[mt][3],
                      bb[nt >> 1][(nt & 1) * 2], bb[nt >> 1][(nt & 1) * 2 + 1]);
    }
}

__global__ __launch_bounds__(256, 2) void gemm_kernel(const float* __restrict__ bias,
                                                      float* __restrict__ Y)
{
    extern __shared__ __half smem[];
    const uint32_t sbase = smem_u32(smem);
    const int tid = threadIdx.x;
    const int wid = tid >> 5, lane = tid & 31;
    const int warp_m = wid & 1, warp_n = wid >> 1;
    const int gid = lane >> 2, tig = lane & 3;

    const int lg = lane >> 3, lr = lane & 7;
    const uint32_t aLane = (uint32_t)(((warp_m * 64 + (lg & 1) * 8 + lr) * PADH
                                       + (lg >> 1) * 8) * 2);
    const uint32_t bLane = (uint32_t)(((warp_n * 32 + (lg >> 1) * 8 + lr) * PADH
                                       + (lg & 1) * 8 + BS_OFF) * 2);

    // first tile: prologue fill
    int tile = blockIdx.x;
    const __half* Ag = g_X + (size_t)((tile >> 4) * BM) * IN_K;
    const __half* Bg = g_W + (size_t)((tile & 15) * BN) * IN_K;
    issue_stage(smem, 0, 0 * BK, Ag, Bg, tid);
    issue_stage(smem, 1, 1 * BK, Ag, Bg, tid);

    while (tile < NTILES) {
        const int bm = (tile >> 4) * BM;
        const int bn = (tile & 15) * BN;
        const int nextTile = tile + NCTA;
        const __half* An = g_X + (size_t)((nextTile >> 4) * BM) * IN_K;
        const __half* Bn = g_W + (size_t)((nextTile & 15) * BN) * IN_K;
        const bool hasNext = (nextTile < NTILES);

        float acc[4][4][4];
#pragma unroll
        for (int i = 0; i < 4; ++i)
#pragma unroll
            for (int j = 0; j < 4; ++j)
#pragma unroll
                for (int q = 0; q < 4; ++q) acc[i][j][q] = 0.f;

        for (int kt = 0; kt < NKT - 1; ++kt) {
            cp_wait<1>();
            __syncthreads();

            const int ldk = kt + 2;
            if (ldk < NKT)
                issue_stage(smem, ldk % NSTG, ldk * BK, Ag, Bg, tid);

            const uint32_t stq = sbase + (uint32_t)(kt % NSTG) * STG_BYTES;
            compute_iter(stq + aLane, stq + bLane, acc);
        }
        {   // final iteration (kt = NKT-1, buffer 1): drain, prefetch next tile
            cp_wait<0>();
            __syncthreads();
            // buffer 0 (kt=30) and buffer 2 (kt=29) fully consumed -> stage 0
            if (hasNext)
                issue_stage(smem, 0, 0 * BK, An, Bn, tid);

            const uint32_t stq = sbase + (uint32_t)((NKT - 1) % NSTG) * STG_BYTES;
            compute_iter(stq + aLane, stq + bLane, acc);

            __syncthreads();   // all warps done with buffer 1 -> stage 1 refill
            if (hasNext)
                issue_stage(smem, 1, 1 * BK, An, Bn, tid);
        }

        // ---- epilogue: bias + store (overlaps next tile's cp.async) ----
#pragma unroll
        for (int mt = 0; mt < 4; ++mt) {
            const int row0 = bm + warp_m * 64 + mt * 16 + gid;
#pragma unroll
            for (int nt = 0; nt < 4; ++nt) {
                const int col = bn + warp_n * 32 + nt * 8 + tig * 2;
                const float bx = __ldg(&bias[col]);
                const float by = __ldg(&bias[col + 1]);
                float2 v0 = make_float2(acc[mt][nt][0] + bx, acc[mt][nt][1] + by);
                float2 v1 = make_float2(acc[mt][nt][2] + bx, acc[mt][nt][3] + by);
                *(float2*)&Y[(size_t)row0 * OUT_N + col] = v0;
                *(float2*)&Y[(size_t)(row0 + 8) * OUT_N + col] = v1;
            }
        }

        tile = nextTile;
        Ag = An;
        Bg = Bn;
    }
}

// ---------------- launch ----------------------------------------------------
extern "C" void kernel_launch(void* const* d_in, const int* in_sizes, int n_in,
                              void* d_out, int out_size)
{
    const float* x       = (const float*)d_in[0];  // [4, 2048, 2048]
    const int*   indices = (const int*)  d_in[1];  // [2048, 2048]
    const float* lut     = (const float*)d_in[2];  // [16]
    const float* sA      = (const float*)d_in[3];  // [2048, 4]
    const float* sB      = (const float*)d_in[4];  // [4, 2048]
    const float* mag     = (const float*)d_in[5];  // [4]
    const float* bias    = (const float*)d_in[6];  // [2048]
    float* y = (float*)d_out;                      // [4, 2048, 2048]

    cudaFuncSetAttribute(gemm_kernel, cudaFuncAttributeMaxDynamicSharedMemorySize, DYN_SMEM);

    prep_fused_kernel<<<PREP_GRID, 256>>>(indices, lut, sA, sB, mag, x);
    gemm_kernel<<<NCTA, 256, DYN_SMEM>>>(bias, y);
}